// round 13
// baseline (speedup 1.0000x reference)
#include <cuda_runtime.h>
#include <cuda_bf16.h>
#include <math.h>

// Problem constants
#define PC_SRC   64000
#define REF_SRC  80000
#define N_PC     8000
#define N_REF    10000

#define GRID     592           // 4 blocks/SM x 148 SMs, all co-resident
#define THREADS  256
#define NPT      3             // points per thread
#define PTS      (THREADS * NPT)   // 768 points per chunk

// Direction A: P = pc (8000), R = ref (10000): 11 x-chunks * 53 y-tiles = 583
#define XC_A     11
#define YT_A     53
#define TILE_A   190
#define HTILE_A  95
#define NCHUNK_A 583
// Direction B: P = ref (10000), R = pc (8000): 14 x-chunks * 42 y-tiles = 588
#define XC_B     14
#define YT_B     42
#define TILE_B   192
#define HTILE_B  96
#define NCHUNK_B 588

#define FINF __int_as_float(0x7F800000)

// Device-global scratch (allocation forbidden)
__device__ float4   g_pcS[N_PC];    // (-2x, -2y, |c|^2, 0), centered at 0.5
__device__ float4   g_refS[N_REF];
__device__ unsigned g_min1[N_PC];   // min squared dist, uint bits (clamped >= 0)
__device__ unsigned g_min2[N_REF];
__device__ double   g_sum;
__device__ unsigned g_bar1, g_bar2, g_done;

typedef unsigned long long ull;

union U64 { ull u; float2 f; };

static __device__ __forceinline__ ull pack2(float lo, float hi) {
    U64 v; v.f = make_float2(lo, hi); return v.u;
}
static __device__ __forceinline__ ull fma2(ull a, ull b, ull c) {
    ull d; asm("fma.rn.f32x2 %0, %1, %2, %3;" : "=l"(d) : "l"(a), "l"(b), "l"(c));
    return d;
}

// Per-chunk compute: NPT points/thread vs one staged tile; RED.MIN result.
template <int HTILE>
static __device__ __forceinline__ void run_chunk(
    const float4* __restrict__ P, unsigned* __restrict__ gmin,
    const ulonglong2* __restrict__ sXY, const ull* __restrict__ sZ,
    int np, int xc, int tid)
{
    const int ib = xc * PTS + tid;
    ull px2[NPT], py2[NPT];
    float pp[NPT];
#pragma unroll
    for (int k = 0; k < NPT; k++) {
        int i = ib + k * THREADS;
        float4 p = P[(i < np) ? i : (np - 1)];
        float x = -0.5f * p.x, y = -0.5f * p.y;
        px2[k] = pack2(x, x);
        py2[k] = pack2(y, y);
        pp[k]  = p.z;
    }

    float mA[NPT], mB[NPT];
#pragma unroll
    for (int k = 0; k < NPT; k++) { mA[k] = FINF; mB[k] = FINF; }

#pragma unroll 4
    for (int j = 0; j < HTILE; j++) {
        ulonglong2 xy = sXY[j];     // (rx2, ry2) packed
        ull rz2 = sZ[j];
#pragma unroll
        for (int k = 0; k < NPT; k++) {
            U64 t; t.u = fma2(px2[k], xy.x, fma2(py2[k], xy.y, rz2));
            mA[k] = fminf(mA[k], t.f.x);
            mB[k] = fminf(mB[k], t.f.y);
        }
    }

#pragma unroll
    for (int k = 0; k < NPT; k++) {
        int i = ib + k * THREADS;
        if (i < np) {
            float v = fmaxf(pp[k] + fminf(mA[k], mB[k]), 0.0f);
            atomicMin(&gmin[i], __float_as_uint(v));   // RED.MIN, no return
        }
    }
}

// Stage one packed tile (caller picks which threads execute this).
static __device__ __forceinline__ void stage_tile(
    const float4* __restrict__ R, int nr, int rbase,
    ulonglong2* __restrict__ sXY, ull* __restrict__ sZ, int lane)
{
    int r0 = rbase + 2 * lane, r1 = r0 + 1;
    float4 a = (r0 < nr) ? R[r0] : make_float4(0.f, 0.f, 1e30f, 0.f);
    float4 b = (r1 < nr) ? R[r1] : make_float4(0.f, 0.f, 1e30f, 0.f);
    sXY[lane] = make_ulonglong2(pack2(a.x, b.x), pack2(a.y, b.y));
    sZ[lane]  = pack2(a.z, b.z);
}

__global__ void __launch_bounds__(THREADS, 4) chamfer_kernel(
    const float* __restrict__ pc_src, const float* __restrict__ ref_src,
    float* __restrict__ out)
{
    const int tid = threadIdx.x;
    const int bid = blockIdx.x;
    const int gtid = bid * THREADS + tid;
    const bool leader = (tid == 0);

    __shared__ ulonglong2 sXY_A[HTILE_A], sXY_B[HTILE_B];
    __shared__ ull        sZ_A[HTILE_A],  sZ_B[HTILE_B];
    __shared__ double warp_s[8];

    // ---- Phase 0: stage subsampled/centered/preprocessed points + init mins
    if (gtid < N_PC) {
        float delta = (float)(PC_SRC - 1) / (float)(N_PC - 1);  // fp32 linspace
        int idx = (int)((float)gtid * delta);                   // fp32 mul+trunc
        if (idx > PC_SRC - 1) idx = PC_SRC - 1;
        float x = pc_src[2 * idx] - 0.5f, y = pc_src[2 * idx + 1] - 0.5f;
        g_pcS[gtid] = make_float4(-2.0f * x, -2.0f * y, fmaf(x, x, y * y), 0.0f);
        g_min1[gtid] = 0x7F800000u;
    }
    if (gtid < N_REF) {
        float delta = (float)(REF_SRC - 1) / (float)(N_REF - 1);
        int idx = (int)((float)gtid * delta);
        if (idx > REF_SRC - 1) idx = REF_SRC - 1;
        float x = ref_src[2 * idx] - 0.5f, y = ref_src[2 * idx + 1] - 0.5f;
        g_refS[gtid] = make_float4(-2.0f * x, -2.0f * y, fmaf(x, x, y * y), 0.0f);
        g_min2[gtid] = 0x7F800000u;
    }
    __threadfence();
    __syncthreads();
    if (leader) {
        atomicAdd(&g_bar1, 1u);
        while (*((volatile unsigned*)&g_bar1) < GRID) __nanosleep(32);
    }
    __syncthreads();

    // ---- Phase 1: at most one A-chunk + one B-chunk per block (near-perfect balance)
    const bool hasA = (bid < NCHUNK_A);
    const bool hasB = (bid < NCHUNK_B);
    const int xcA = bid % XC_A, ycA = bid / XC_A;
    const int xcB = bid % XC_B, ycB = bid / XC_B;

    // stage both tiles concurrently with different warps, one barrier total
    if (tid < HTILE_A) {
        if (hasA) stage_tile(g_refS, N_REF, ycA * TILE_A, sXY_A, sZ_A, tid);
    } else if (tid >= 128 && tid < 128 + HTILE_B) {
        if (hasB) stage_tile(g_pcS, N_PC, ycB * TILE_B, sXY_B, sZ_B, tid - 128);
    }
    __syncthreads();

    if (hasA) run_chunk<HTILE_A>(g_pcS, g_min1, sXY_A, sZ_A, N_PC, xcA, tid);
    if (hasB) run_chunk<HTILE_B>(g_refS, g_min2, sXY_B, sZ_B, N_REF, xcB, tid);

    // ---- barrier 2 (all RED.MINs visible)
    __threadfence();
    __syncthreads();
    if (leader) {
        atomicAdd(&g_bar2, 1u);
        while (*((volatile unsigned*)&g_bar2) < GRID) __nanosleep(32);
    }
    __syncthreads();

    // ---- Phase 2: finish (one load + sqrt per point, 18000 pts)
    double local = 0.0;
    if (gtid < N_PC + N_REF) {
        if (gtid < N_PC)
            local = (double)sqrtf(__uint_as_float(__ldcg(&g_min1[gtid])))
                    * (0.5 / (double)N_PC);
        else
            local = (double)sqrtf(__uint_as_float(__ldcg(&g_min2[gtid - N_PC])))
                    * (0.5 / (double)N_REF);
    }
    for (int off = 16; off > 0; off >>= 1)
        local += __shfl_down_sync(0xFFFFFFFFu, local, off);
    const int wid = tid >> 5, lid = tid & 31;
    if (lid == 0) warp_s[wid] = local;
    __syncthreads();
    if (wid == 0) {
        local = (lid < 8) ? warp_s[lid] : 0.0;
        for (int off = 4; off > 0; off >>= 1)
            local += __shfl_down_sync(0xFFFFFFFFu, local, off);
        if (lid == 0) {
            if (local != 0.0) atomicAdd(&g_sum, local);
            __threadfence();
            unsigned t = atomicAdd(&g_done, 1u);
            if (t == GRID - 1) {
                // last block: publish + reset ALL state for next graph replay
                double s = *((volatile double*)&g_sum);
                out[0] = (float)s;
                g_sum = 0.0;
                g_bar1 = 0u; g_bar2 = 0u; g_done = 0u;
                __threadfence();
            }
        }
    }
}

extern "C" void kernel_launch(void* const* d_in, const int* in_sizes, int n_in,
                              void* d_out, int out_size)
{
    const float* pc_src  = (const float*)d_in[0];  // (1000,64,2) fp32
    const float* ref_src = (const float*)d_in[1];  // (80000,2)  fp32
    float* out = (float*)d_out;

    chamfer_kernel<<<GRID, THREADS>>>(pc_src, ref_src, out);
}